// round 2
// baseline (speedup 1.0000x reference)
#include <cuda_runtime.h>
#include <cuda_bf16.h>

// pred, true: [B=2, C=16, D=64, H=128, W=128] f32 ; weight: [16] f32 ; out: scalar f32
// result = ( sum_i w[class(i)] * bce_i ) / (sum_w * B*D*H*W)
// Layout [B,C,D,H,W]: each contiguous SPATIAL=1,048,576-element segment is one
// class (seg % 16). Single-kernel threadfence reduction: last block finalizes.

#define SPATIAL        (64 * 128 * 128)   // 1,048,576
#define N_SEGS         (2 * 16)           // 32
#define C_CLASSES      16
#define BLOCKS_PER_SEG 64
#define NBLOCKS        (N_SEGS * BLOCKS_PER_SEG)   // 2048
#define THREADS        256
#define F4_PER_SEG     (SPATIAL / 4)                      // 262,144
#define F4_PER_BLOCK   (F4_PER_SEG / BLOCKS_PER_SEG)      // 4,096
#define F4_PER_THREAD  (F4_PER_BLOCK / THREADS)           // 16

__device__ double       g_partials[NBLOCKS];
__device__ unsigned int g_count = 0;   // last block resets to 0 -> replay-safe

__device__ __forceinline__ float bce_elem(float p, float t) {
    // torch F.binary_cross_entropy clamps log terms at -100
    float lp = fmaxf(__logf(p), -100.0f);
    float l1 = fmaxf(__logf(1.0f - p), -100.0f);
    return -fmaf(t, lp - l1, l1);       // -(t*lp + (1-t)*l1)
}

__global__ __launch_bounds__(THREADS)
void bce_reduce_kernel(const float4* __restrict__ pred,
                       const float4* __restrict__ tru,
                       const float*  __restrict__ weight,
                       float* __restrict__ out) {
    const int seg = blockIdx.x / BLOCKS_PER_SEG;
    const int sub = blockIdx.x % BLOCKS_PER_SEG;
    const size_t base = (size_t)seg * F4_PER_SEG + (size_t)sub * F4_PER_BLOCK
                      + threadIdx.x;

    float acc = 0.0f;
    #pragma unroll
    for (int k = 0; k < F4_PER_THREAD; k++) {
        float4 p = __ldg(&pred[base + (size_t)k * THREADS]);
        float4 t = __ldg(&tru [base + (size_t)k * THREADS]);
        acc += bce_elem(p.x, t.x);
        acc += bce_elem(p.y, t.y);
        acc += bce_elem(p.z, t.z);
        acc += bce_elem(p.w, t.w);
    }

    // warp reduce
    #pragma unroll
    for (int off = 16; off > 0; off >>= 1)
        acc += __shfl_xor_sync(0xFFFFFFFFu, acc, off);

    __shared__ float warp_sums[THREADS / 32];
    const int lane = threadIdx.x & 31;
    const int wid  = threadIdx.x >> 5;
    if (lane == 0) warp_sums[wid] = acc;
    __syncthreads();

    __shared__ bool is_last;
    if (threadIdx.x == 0) {
        float v = 0.0f;
        #pragma unroll
        for (int w = 0; w < THREADS / 32; w++) v += warp_sums[w];
        const float wc = __ldg(&weight[seg % C_CLASSES]);
        g_partials[blockIdx.x] = (double)v * (double)wc;
        __threadfence();
        unsigned int ticket = atomicAdd(&g_count, 1u);
        is_last = (ticket == NBLOCKS - 1);
    }
    __syncthreads();

    if (is_last) {
        // reduce 2048 double partials with 256 threads (8 each)
        double d = 0.0;
        #pragma unroll
        for (int k = 0; k < NBLOCKS / THREADS; k++)
            d += g_partials[threadIdx.x + k * THREADS];

        // warp reduce doubles
        #pragma unroll
        for (int off = 16; off > 0; off >>= 1)
            d += __shfl_xor_sync(0xFFFFFFFFu, d, off);

        __shared__ double dwarp[THREADS / 32];
        if (lane == 0) dwarp[wid] = d;
        __syncthreads();

        if (threadIdx.x == 0) {
            double total = 0.0;
            #pragma unroll
            for (int w = 0; w < THREADS / 32; w++) total += dwarp[w];
            double sum_w = 0.0;
            #pragma unroll
            for (int c = 0; c < C_CLASSES; c++) sum_w += (double)__ldg(&weight[c]);
            const double denom = sum_w * (double)(2.0 * 64.0 * 128.0 * 128.0);
            out[0] = (float)(total / denom);
            g_count = 0;   // reset for next graph replay
        }
    }
}

extern "C" void kernel_launch(void* const* d_in, const int* in_sizes, int n_in,
                              void* d_out, int out_size) {
    const float4* pred = (const float4*)d_in[0];
    const float4* tru  = (const float4*)d_in[1];
    const float*  w    = (const float*)d_in[2];
    bce_reduce_kernel<<<NBLOCKS, THREADS>>>(pred, tru, w, (float*)d_out);
}

// round 3
// speedup vs baseline: 1.2597x; 1.2597x over previous
#include <cuda_runtime.h>
#include <cuda_bf16.h>

// pred, true: [B=2, C=16, D=64, H=128, W=128] f32 ; weight: [16] f32 ; out: scalar f32
// result = ( sum_i w[class(i)] * bce_i ) / (sum_w * B*D*H*W)
// Each contiguous SPATIAL=1,048,576-element segment is one class (seg % 16).
// Single-kernel: blocks write weighted double partials; last block (atomic
// ticket) reduces them, writes out, resets counter (graph-replay safe).
//
// Math done in log2 domain: bce/ln2 = -(t*(lg2 p - lg2 q) + lg2 q), q=1-p.
// Clamp at -100/ln2 = -144.269504. One MUFU LG2 per log, no per-element FMUL.

#define SPATIAL        (64 * 128 * 128)   // 1,048,576
#define N_SEGS         (2 * 16)           // 32
#define C_CLASSES      16
#define BLOCKS_PER_SEG 32
#define NBLOCKS        (N_SEGS * BLOCKS_PER_SEG)   // 1024
#define THREADS        256
#define F4_PER_SEG     (SPATIAL / 4)                      // 262,144
#define F4_PER_BLOCK   (F4_PER_SEG / BLOCKS_PER_SEG)      // 8,192
#define F4_PER_THREAD  (F4_PER_BLOCK / THREADS)           // 32 (128 elems/thread)

#define LN2      0.6931471805599453
#define CLAMP_L2 (-144.269504f)   // -100 / ln2

__device__ double       g_partials[NBLOCKS];
__device__ unsigned int g_count = 0;

__device__ __forceinline__ float bce_l2(float p, float t) {
    float a = fmaxf(__log2f(p), CLAMP_L2);
    float b = fmaxf(__log2f(1.0f - p), CLAMP_L2);
    return -fmaf(t, a - b, b);            // bce / ln2
}

__device__ __forceinline__ float bce4_l2(float4 p, float4 t) {
    return bce_l2(p.x, t.x) + bce_l2(p.y, t.y)
         + bce_l2(p.z, t.z) + bce_l2(p.w, t.w);
}

__global__ __launch_bounds__(THREADS)
void bce_reduce_kernel(const float4* __restrict__ pred,
                       const float4* __restrict__ tru,
                       const float*  __restrict__ weight,
                       float* __restrict__ out) {
    const int seg = blockIdx.x / BLOCKS_PER_SEG;
    const int sub = blockIdx.x % BLOCKS_PER_SEG;
    const size_t base = (size_t)seg * F4_PER_SEG + (size_t)sub * F4_PER_BLOCK
                      + threadIdx.x;

    // depth-2 software pipeline: next iteration's loads in flight during compute
    float4 p0 = __ldg(&pred[base]);
    float4 t0 = __ldg(&tru [base]);
    float acc = 0.0f;

    #pragma unroll 4
    for (int k = 1; k < F4_PER_THREAD; k++) {
        float4 p1 = __ldg(&pred[base + (size_t)k * THREADS]);
        float4 t1 = __ldg(&tru [base + (size_t)k * THREADS]);
        acc += bce4_l2(p0, t0);
        p0 = p1; t0 = t1;
    }
    acc += bce4_l2(p0, t0);

    // warp reduce
    #pragma unroll
    for (int off = 16; off > 0; off >>= 1)
        acc += __shfl_xor_sync(0xFFFFFFFFu, acc, off);

    __shared__ float warp_sums[THREADS / 32];
    const int lane = threadIdx.x & 31;
    const int wid  = threadIdx.x >> 5;
    if (lane == 0) warp_sums[wid] = acc;
    __syncthreads();

    __shared__ bool is_last;
    if (threadIdx.x == 0) {
        float v = 0.0f;
        #pragma unroll
        for (int w = 0; w < THREADS / 32; w++) v += warp_sums[w];
        const float wc = __ldg(&weight[seg % C_CLASSES]);
        // fold ln2 (log2 -> ln) into the per-block partial
        g_partials[blockIdx.x] = (double)v * (double)wc * LN2;
        __threadfence();
        unsigned int ticket = atomicAdd(&g_count, 1u);
        is_last = (ticket == NBLOCKS - 1);
    }
    __syncthreads();

    if (is_last) {
        // reduce 1024 double partials with 256 threads (4 each)
        double d = 0.0;
        #pragma unroll
        for (int k = 0; k < NBLOCKS / THREADS; k++)
            d += g_partials[threadIdx.x + k * THREADS];

        #pragma unroll
        for (int off = 16; off > 0; off >>= 1)
            d += __shfl_xor_sync(0xFFFFFFFFu, d, off);

        __shared__ double dwarp[THREADS / 32];
        if (lane == 0) dwarp[wid] = d;
        __syncthreads();

        if (threadIdx.x == 0) {
            double total = 0.0;
            #pragma unroll
            for (int w = 0; w < THREADS / 32; w++) total += dwarp[w];
            double sum_w = 0.0;
            #pragma unroll
            for (int c = 0; c < C_CLASSES; c++) sum_w += (double)__ldg(&weight[c]);
            const double denom = sum_w * (double)(2.0 * 64.0 * 128.0 * 128.0);
            out[0] = (float)(total / denom);
            g_count = 0;   // reset for next graph replay
        }
    }
}

extern "C" void kernel_launch(void* const* d_in, const int* in_sizes, int n_in,
                              void* d_out, int out_size) {
    const float4* pred = (const float4*)d_in[0];
    const float4* tru  = (const float4*)d_in[1];
    const float*  w    = (const float*)d_in[2];
    bce_reduce_kernel<<<NBLOCKS, THREADS>>>(pred, tru, w, (float*)d_out);
}